// round 1
// baseline (speedup 1.0000x reference)
#include <cuda_runtime.h>
#include <cuda_bf16.h>
#include <math.h>

// DynamicPatchAggregator:
//   out[c,v] = sum_k wt(v - s_k) * patch[k,c,v - s_k] / (1e-20 + sum_k wt(v - s_k))
// Patch grid is the deterministic 3x3x3 lattice starts = 48*(kd,kh,kw),
// k = kd*9 + kh*3 + kw, which fully covers the 192^3 volume, so the
// trilinear-upsample branch of the reference contributes exactly 0 and the
// global_logit / patch_starts inputs are not needed at runtime.
//
// Gather formulation: each voxel is covered by 1..8 patches; each patch
// element is read exactly once. No atomics, no weight-map buffer.

#define VOLD 192
#define PATCHD 96
#define STRIDED 48
#define NCH 2
#define WGROUPS (VOLD / 4)   // 48 float4 groups along w

__global__ __launch_bounds__(256)
void dpa_gather_kernel(const float* __restrict__ patches,
                       float* __restrict__ out)
{
    // 1-D gaussian table, sigma = 0.125*96 = 12, center = 48, max-normalized (max = 1).
    __shared__ float G[PATCHD];
    {
        int t = threadIdx.x;
        if (t < PATCHD) {
            float x = (float)(t - 48);
            G[t] = expf(-x * x * (1.0f / 288.0f));   // exp(-0.5*(x/12)^2)
        }
    }
    __syncthreads();

    long long gid = (long long)blockIdx.x * blockDim.x + threadIdx.x;
    // total float4 groups = 192*192*48 = 1,769,472 (exact multiple of 256*6912)
    int wg = (int)(gid % WGROUPS);
    int h  = (int)((gid / WGROUPS) % VOLD);
    int d  = (int)(gid / ((long long)WGROUPS * VOLD));
    int w  = wg * 4;

    // covering patch indices per axis: {id-1, id} clamped to [0,2]
    int idd = d / STRIDED;
    int kd0 = idd > 0 ? idd - 1 : 0;
    int kd1 = idd < 3 ? idd : 2;
    int idh = h / STRIDED;
    int kh0 = idh > 0 ? idh - 1 : 0;
    int kh1 = idh < 3 ? idh : 2;
    int idw = w / STRIDED;                 // 48-boundaries are 4-aligned, so the
    int kw0 = idw > 0 ? idw - 1 : 0;       // kw set is uniform across the float4
    int kw1 = idw < 3 ? idw : 2;

    float a0x = 0.f, a0y = 0.f, a0z = 0.f, a0w = 0.f;   // channel 0
    float a1x = 0.f, a1y = 0.f, a1z = 0.f, a1w = 0.f;   // channel 1
    float sx = 1e-20f, sy = 1e-20f, sz = 1e-20f, sw = 1e-20f;

    const size_t PCUBE = (size_t)PATCHD * PATCHD * PATCHD;

    for (int kd = kd0; kd <= kd1; ++kd) {
        int od = d - STRIDED * kd;
        float gd = G[od];
        for (int kh = kh0; kh <= kh1; ++kh) {
            int oh = h - STRIDED * kh;
            float gdh = gd * G[oh];
            for (int kw = kw0; kw <= kw1; ++kw) {
                int ow = w - STRIDED * kw;
                float4 g4 = *reinterpret_cast<const float4*>(&G[ow]);
                int k = kd * 9 + kh * 3 + kw;
                size_t base = ((((size_t)k * NCH) * PATCHD + od) * PATCHD + oh) * PATCHD + ow;
                float4 p0 = __ldg(reinterpret_cast<const float4*>(patches + base));
                float4 p1 = __ldg(reinterpret_cast<const float4*>(patches + base + PCUBE));
                float w0 = gdh * g4.x, w1 = gdh * g4.y, w2 = gdh * g4.z, w3 = gdh * g4.w;
                a0x += w0 * p0.x; a0y += w1 * p0.y; a0z += w2 * p0.z; a0w += w3 * p0.w;
                a1x += w0 * p1.x; a1y += w1 * p1.y; a1z += w2 * p1.z; a1w += w3 * p1.w;
                sx += w0; sy += w1; sz += w2; sw += w3;
            }
        }
    }

    float rx = 1.0f / sx, ry = 1.0f / sy, rz = 1.0f / sz, rw = 1.0f / sw;

    size_t obase = ((size_t)d * VOLD + h) * VOLD + w;     // channel 0
    const size_t VCUBE = (size_t)VOLD * VOLD * VOLD;

    float4 r0 = make_float4(a0x * rx, a0y * ry, a0z * rz, a0w * rw);
    float4 r1 = make_float4(a1x * rx, a1y * ry, a1z * rz, a1w * rw);
    *reinterpret_cast<float4*>(out + obase)         = r0;
    *reinterpret_cast<float4*>(out + obase + VCUBE) = r1;
}

extern "C" void kernel_launch(void* const* d_in, const int* in_sizes, int n_in,
                              void* d_out, int out_size)
{
    const float* patches = (const float*)d_in[0];   // [27, 2, 96, 96, 96] f32
    // d_in[1] = global_logit (unused: fully-covered volume -> upsample masked out)
    // d_in[2] = patch_starts (deterministic lattice, baked into index math)
    float* out = (float*)d_out;                     // [1, 2, 192, 192, 192] f32

    const long long total_groups = (long long)VOLD * VOLD * WGROUPS;  // 1,769,472
    int block = 256;
    int grid = (int)((total_groups + block - 1) / block);             // 6912
    dpa_gather_kernel<<<grid, block>>>(patches, out);
}

// round 2
// speedup vs baseline: 1.4948x; 1.4948x over previous
#include <cuda_runtime.h>
#include <cuda_bf16.h>
#include <math.h>

// DynamicPatchAggregator — region-specialized gather.
//
//   out[c,v] = sum_k wt(v-s_k)*patch[k,c,v-s_k] / (1e-20 + sum_k wt(v-s_k))
//
// Deterministic 3x3x3 patch lattice (starts = 48*(kd,kh,kw)) fully covers the
// 192^3 volume, so the trilinear-upsample branch is exactly 0 and only
// patch_logits matters. Per axis, coordinate region r = x/48 in {0,1,2,3}
// determines the covering patch set: r==0 -> {0}, r==1 -> {0,1},
// r==2 -> {1,2}, r==3 -> {2}. Blocks are tiled to sit inside a single region
// triple, so (nd,nh,nw) is block-uniform and we dispatch to one of 8 fully
// unrolled template cases -> all patch loads are independent & front-batched.

#define VOLD 192
#define PATCHD 96
#define STRIDED 48

template<int ND, int NH, int NW>
__device__ __forceinline__ void compute_case(
    const float* __restrict__ patches, float* __restrict__ out,
    const float* __restrict__ G,
    int d, int h, int w, int c, int kd0, int kh0, int kw0)
{
    float wd[ND]; int od[ND];
#pragma unroll
    for (int i = 0; i < ND; ++i) { od[i] = d - STRIDED * (kd0 + i); wd[i] = G[od[i]]; }
    float wh[NH]; int oh[NH];
#pragma unroll
    for (int i = 0; i < NH; ++i) { oh[i] = h - STRIDED * (kh0 + i); wh[i] = G[oh[i]]; }
    float4 gw[NW]; int ow[NW];
#pragma unroll
    for (int i = 0; i < NW; ++i) {
        ow[i] = w - STRIDED * (kw0 + i);
        gw[i] = *reinterpret_cast<const float4*>(G + ow[i]);
    }

    // Front-batched independent loads (<= 8 LDG.128)
    float4 p[ND * NH * NW];
#pragma unroll
    for (int id = 0; id < ND; ++id)
#pragma unroll
        for (int ih = 0; ih < NH; ++ih)
#pragma unroll
            for (int iw = 0; iw < NW; ++iw) {
                int k = (kd0 + id) * 9 + (kh0 + ih) * 3 + (kw0 + iw);
                size_t base = ((((size_t)(k * 2 + c)) * PATCHD + od[id]) * PATCHD
                               + oh[ih]) * PATCHD + ow[iw];
                p[(id * NH + ih) * NW + iw] =
                    __ldg(reinterpret_cast<const float4*>(patches + base));
            }

    float ax = 0.f, ay = 0.f, az = 0.f, aw = 0.f;
#pragma unroll
    for (int id = 0; id < ND; ++id)
#pragma unroll
        for (int ih = 0; ih < NH; ++ih) {
            float wdh = wd[id] * wh[ih];
#pragma unroll
            for (int iw = 0; iw < NW; ++iw) {
                float4 v = p[(id * NH + ih) * NW + iw];
                float4 g = gw[iw];
                ax += wdh * g.x * v.x;
                ay += wdh * g.y * v.y;
                az += wdh * g.z * v.z;
                aw += wdh * g.w * v.w;
            }
        }

    // weight sum factorizes: (sum wd)(sum wh)(sum gw[i])
    float sd = 0.f, sh = 0.f;
#pragma unroll
    for (int i = 0; i < ND; ++i) sd += wd[i];
#pragma unroll
    for (int i = 0; i < NH; ++i) sh += wh[i];
    float gsx = 0.f, gsy = 0.f, gsz = 0.f, gsw = 0.f;
#pragma unroll
    for (int i = 0; i < NW; ++i) { gsx += gw[i].x; gsy += gw[i].y; gsz += gw[i].z; gsw += gw[i].w; }
    float f = sd * sh;

    float4 r;
    r.x = ax / (f * gsx + 1e-20f);
    r.y = ay / (f * gsy + 1e-20f);
    r.z = az / (f * gsz + 1e-20f);
    r.w = aw / (f * gsw + 1e-20f);

    size_t obase = (((size_t)c * VOLD + d) * VOLD + h) * VOLD + w;
    *reinterpret_cast<float4*>(out + obase) = r;
}

__global__ __launch_bounds__(192, 4)
void dpa_region_kernel(const float* __restrict__ patches,
                       float* __restrict__ out)
{
    __shared__ __align__(16) float G[PATCHD];
    if (threadIdx.x < PATCHD) {
        float x = (float)((int)threadIdx.x - 48);
        G[threadIdx.x] = expf(-x * x * (1.0f / 288.0f));  // sigma=12, center=48
    }
    __syncthreads();

    int t   = threadIdx.x;
    int wgl = t % 12;          // w-group within 48-wide region (12 float4 groups)
    int hl  = t / 12;          // 16 h rows
    int d   = blockIdx.x;                       // 192
    int h   = blockIdx.y * 16 + hl;             // 12 tiles of 16 (tiles don't cross 48-regions)
    int z   = blockIdx.z;                       // 8 = 4 w-regions x 2 channels
    int c   = z >> 2;
    int w   = (z & 3) * STRIDED + wgl * 4;

    int rd = d / STRIDED, rh = h / STRIDED, rw = (z & 3);
    int kd0 = (rd == 0) ? 0 : rd - 1;  int nd = (rd == 1 || rd == 2) ? 2 : 1;
    int kh0 = (rh == 0) ? 0 : rh - 1;  int nh = (rh == 1 || rh == 2) ? 2 : 1;
    int kw0 = (rw == 0) ? 0 : rw - 1;  int nw = (rw == 1 || rw == 2) ? 2 : 1;

    // block-uniform dispatch (d, h-tile, w-region, c are all per-block)
    int combo = ((nd - 1) << 2) | ((nh - 1) << 1) | (nw - 1);
    switch (combo) {
        case 0: compute_case<1,1,1>(patches, out, G, d, h, w, c, kd0, kh0, kw0); break;
        case 1: compute_case<1,1,2>(patches, out, G, d, h, w, c, kd0, kh0, kw0); break;
        case 2: compute_case<1,2,1>(patches, out, G, d, h, w, c, kd0, kh0, kw0); break;
        case 3: compute_case<1,2,2>(patches, out, G, d, h, w, c, kd0, kh0, kw0); break;
        case 4: compute_case<2,1,1>(patches, out, G, d, h, w, c, kd0, kh0, kw0); break;
        case 5: compute_case<2,1,2>(patches, out, G, d, h, w, c, kd0, kh0, kw0); break;
        case 6: compute_case<2,2,1>(patches, out, G, d, h, w, c, kd0, kh0, kw0); break;
        default: compute_case<2,2,2>(patches, out, G, d, h, w, c, kd0, kh0, kw0); break;
    }
}

extern "C" void kernel_launch(void* const* d_in, const int* in_sizes, int n_in,
                              void* d_out, int out_size)
{
    const float* patches = (const float*)d_in[0];   // [27,2,96,96,96] f32
    // d_in[1] global_logit, d_in[2] patch_starts: unused (full coverage, fixed lattice)
    float* out = (float*)d_out;                     // [1,2,192,192,192] f32

    dim3 grid(VOLD, VOLD / 16, 8);   // d, h-tiles, (w-region x channel)
    dim3 block(192);                 // 12 w-groups x 16 h rows
    dpa_region_kernel<<<grid, block>>>(patches, out);
}